// round 1
// baseline (speedup 1.0000x reference)
#include <cuda_runtime.h>

#define NN 100000
#define NE 1000000
#define NGR 512

// ---------------- scratch (device globals; no allocation allowed) ----------------
__device__ float g_we[NE];        // per-edge combined weight
__device__ float g_Win[NN];       // sum of incoming edge weights
__device__ float g_atts[NN];      // attention sum (src+dst)
__device__ float g_deg[NN];       // degree (both endpoints)
__device__ int   g_cnt[NN];       // in-degree (CSR row counts)
__device__ int   g_rs[NN];        // CSR row start
__device__ int   g_cur[NN];       // CSR fill cursor
__device__ int   g_bsum[128];     // scan block sums
__device__ int   g_csrc[NE];      // CSR: source node per slot
__device__ float g_csw[NE];       // CSR: edge weight per slot
__device__ float g_h[NN * 64];
__device__ float g_A[NN * 64];
__device__ float g_D[NN * 64];
__device__ float g_gx[NGR * 64];

// ---------------- zero init ----------------
__global__ void k_zero() {
    int i = blockIdx.x * 256 + threadIdx.x;
    if (i < NN) { g_Win[i] = 0.f; g_atts[i] = 0.f; g_deg[i] = 0.f; g_cnt[i] = 0; }
}

// ---------------- node embedding: h = x @ W(4x64) + b ----------------
__global__ void k_embed(const float* __restrict__ x, const float* __restrict__ w,
                        const float* __restrict__ b) {
    int gid = blockIdx.x * 256 + threadIdx.x;
    if (gid >= NN * 64) return;
    int i = gid >> 6, c = gid & 63;
    float x0 = x[i * 4], x1 = x[i * 4 + 1], x2 = x[i * 4 + 2], x3 = x[i * 4 + 3];
    g_h[gid] = b[c] + x0 * w[c] + x1 * w[64 + c] + x2 * w[128 + c] + x3 * w[192 + c];
}

// ---------------- edge stats + in-degree histogram ----------------
__global__ void k_edge(const int* __restrict__ src, const int* __restrict__ dst,
                       const float* __restrict__ attr, const float* __restrict__ atten) {
    int e = blockIdx.x * 256 + threadIdx.x;
    if (e >= NE) return;
    int s = src[e], d = dst[e];
    float at = atten[e];
    float w = attr[e] * at;
    g_we[e] = w;
    atomicAdd(&g_Win[d], w);
    atomicAdd(&g_atts[d], at);
    atomicAdd(&g_atts[s], at);
    atomicAdd(&g_deg[d], 1.f);
    atomicAdd(&g_deg[s], 1.f);
    atomicAdd(&g_cnt[d], 1);
}

// ---------------- exclusive scan of g_cnt -> g_rs (3 phases) ----------------
__global__ void k_scan1() {
    int tid = threadIdx.x;
    int base = blockIdx.x * 1024 + tid * 4;
    int v0 = 0, v1 = 0, v2 = 0, v3 = 0;
    if (base + 3 < NN) {
        int4 t = *(const int4*)&g_cnt[base];
        v0 = t.x; v1 = t.y; v2 = t.z; v3 = t.w;
    } else {
        if (base < NN)     v0 = g_cnt[base];
        if (base + 1 < NN) v1 = g_cnt[base + 1];
        if (base + 2 < NN) v2 = g_cnt[base + 2];
        if (base + 3 < NN) v3 = g_cnt[base + 3];
    }
    int sloc = v0 + v1 + v2 + v3;
    int x = sloc;
#pragma unroll
    for (int o = 1; o < 32; o <<= 1) {
        int y = __shfl_up_sync(0xffffffffu, x, o);
        if ((tid & 31) >= o) x += y;
    }
    __shared__ int wsum[8];
    if ((tid & 31) == 31) wsum[tid >> 5] = x;
    __syncthreads();
    if (tid < 8) {
        int y = wsum[tid];
#pragma unroll
        for (int o = 1; o < 8; o <<= 1) {
            int z = __shfl_up_sync(0xffu, y, o);
            if (tid >= o) y += z;
        }
        wsum[tid] = y;
    }
    __syncthreads();
    int woff = (tid >= 32) ? wsum[(tid >> 5) - 1] : 0;
    int excl = x - sloc + woff;
    if (base < NN)     g_rs[base]     = excl;
    if (base + 1 < NN) g_rs[base + 1] = excl + v0;
    if (base + 2 < NN) g_rs[base + 2] = excl + v0 + v1;
    if (base + 3 < NN) g_rs[base + 3] = excl + v0 + v1 + v2;
    if (tid == 255) g_bsum[blockIdx.x] = excl + sloc;
}

__global__ void k_scan2(int nb) {
    int tid = threadIdx.x;  // 128 threads
    int v = (tid < nb) ? g_bsum[tid] : 0;
    int x = v;
#pragma unroll
    for (int o = 1; o < 32; o <<= 1) {
        int y = __shfl_up_sync(0xffffffffu, x, o);
        if ((tid & 31) >= o) x += y;
    }
    __shared__ int ws[4];
    if ((tid & 31) == 31) ws[tid >> 5] = x;
    __syncthreads();
    int add = 0;
    for (int wq = 0; wq < (tid >> 5); wq++) add += ws[wq];
    x += add;
    if (tid < nb) g_bsum[tid] = x - v;  // exclusive
}

__global__ void k_scan3() {
    int i = blockIdx.x * 256 + threadIdx.x;
    if (i < NN) {
        int r = g_rs[i] + g_bsum[i >> 10];
        g_rs[i] = r;
        g_cur[i] = r;
    }
}

// ---------------- CSR fill ----------------
__global__ void k_fill(const int* __restrict__ src, const int* __restrict__ dst) {
    int e = blockIdx.x * 256 + threadIdx.x;
    if (e >= NE) return;
    int d = dst[e];
    int p = atomicAdd(&g_cur[d], 1);
    g_csrc[p] = src[e];
    g_csw[p] = g_we[e];
}

// ---------------- layer GEMM: A = h@W1+b1 ; D = h@W3+b3 - Win*(h@W2) ----------------
// block: 128 nodes x 64 cols, 256 threads, register tile 8x4.
__global__ void __launch_bounds__(256) k_gemm(const float* __restrict__ W1,
                                              const float* __restrict__ W2,
                                              const float* __restrict__ W3,
                                              const float* __restrict__ b1,
                                              const float* __restrict__ b3) {
    extern __shared__ float sm[];
    float* sh_h = sm;            // [128][68] padded
    float* sh_w = sm + 128 * 68; // [64][64]
    int tid = threadIdx.x;
    int nb = blockIdx.x * 128;

    for (int i = tid; i < 2048; i += 256) {  // 128*64 floats as float4
        int node = i >> 4, k4 = (i & 15) << 2;
        float4 v = make_float4(0.f, 0.f, 0.f, 0.f);
        int gn = nb + node;
        if (gn < NN) v = *(const float4*)&g_h[gn * 64 + k4];
        *(float4*)&sh_h[node * 68 + k4] = v;
    }

    int c4 = (tid & 15) << 2;
    int r0 = (tid >> 4) << 3;
    float4 acc2[8];
#pragma unroll
    for (int j = 0; j < 8; j++) acc2[j] = make_float4(0.f, 0.f, 0.f, 0.f);

    for (int m = 0; m < 3; m++) {
        const float* Wm = (m == 0) ? W1 : ((m == 1) ? W2 : W3);
        __syncthreads();
        for (int i = tid; i < 1024; i += 256)
            ((float4*)sh_w)[i] = ((const float4*)Wm)[i];
        __syncthreads();

        float4 acc[8];
#pragma unroll
        for (int j = 0; j < 8; j++) acc[j] = make_float4(0.f, 0.f, 0.f, 0.f);

#pragma unroll 4
        for (int k = 0; k < 64; k++) {
            float4 w = *(const float4*)&sh_w[k * 64 + c4];
#pragma unroll
            for (int j = 0; j < 8; j++) {
                float hv = sh_h[(r0 + j) * 68 + k];
                acc[j].x = fmaf(hv, w.x, acc[j].x);
                acc[j].y = fmaf(hv, w.y, acc[j].y);
                acc[j].z = fmaf(hv, w.z, acc[j].z);
                acc[j].w = fmaf(hv, w.w, acc[j].w);
            }
        }

        if (m == 0) {
            float4 bb = *(const float4*)&b1[c4];
#pragma unroll
            for (int j = 0; j < 8; j++) {
                int gn = nb + r0 + j;
                if (gn < NN) {
                    float4 o = make_float4(acc[j].x + bb.x, acc[j].y + bb.y,
                                           acc[j].z + bb.z, acc[j].w + bb.w);
                    *(float4*)&g_A[gn * 64 + c4] = o;
                }
            }
        } else if (m == 1) {
#pragma unroll
            for (int j = 0; j < 8; j++) acc2[j] = acc[j];
        } else {
            float4 bb = *(const float4*)&b3[c4];
#pragma unroll
            for (int j = 0; j < 8; j++) {
                int gn = nb + r0 + j;
                if (gn < NN) {
                    float win = g_Win[gn];
                    float4 o = make_float4(acc[j].x + bb.x - win * acc2[j].x,
                                           acc[j].y + bb.y - win * acc2[j].y,
                                           acc[j].z + bb.z - win * acc2[j].z,
                                           acc[j].w + bb.w - win * acc2[j].w);
                    *(float4*)&g_D[gn * 64 + c4] = o;
                }
            }
        }
    }
}

// ---------------- gather: h = relu( sum_e w*A[src] + D ), warp per node ----------------
__global__ void k_gather() {
    int gt = blockIdx.x * 256 + threadIdx.x;
    int node = gt >> 5, lane = gt & 31;
    if (node >= NN) return;
    int s = g_rs[node];
    int e = s + g_cnt[node];
    float ax = 0.f, ay = 0.f;
    for (int base = s; base < e; base += 32) {
        int idx = base + lane;
        int sn = 0; float wv = 0.f;
        if (idx < e) { sn = g_csrc[idx]; wv = g_csw[idx]; }
        int m = min(32, e - base);
        for (int j = 0; j < m; j++) {
            int ss = __shfl_sync(0xffffffffu, sn, j);
            float ww = __shfl_sync(0xffffffffu, wv, j);
            float2 av = *(const float2*)&g_A[ss * 64 + lane * 2];
            ax = fmaf(ww, av.x, ax);
            ay = fmaf(ww, av.y, ay);
        }
    }
    float2 dv = *(const float2*)&g_D[node * 64 + lane * 2];
    float2 hv = make_float2(fmaxf(ax + dv.x, 0.f), fmaxf(ay + dv.y, 0.f));
    *(float2*)&g_h[node * 64 + lane * 2] = hv;
}

// ---------------- pooling (batch sorted -> binary search, no atomics) ----------------
__global__ void k_pool(const int* __restrict__ batch) {
    int g = blockIdx.x, tid = threadIdx.x;  // 64 threads
    __shared__ int se[2];
    if (tid < 2) {
        int key = g + tid;
        int lo = 0, hi = NN;
        while (lo < hi) {
            int mid = (lo + hi) >> 1;
            if (batch[mid] < key) lo = mid + 1; else hi = mid;
        }
        se[tid] = lo;
    }
    __syncthreads();
    int s = se[0], e = se[1];
    float acc = 0.f, att = 0.f;
    for (int i = s; i < e; i++) {
        float dg = g_deg[i];
        float na = g_atts[i] / ((dg == 0.f) ? 1.f : dg);
        acc = fmaf(g_h[i * 64 + tid], na, acc);
        att += na;
    }
    float cnt = (float)(e - s);
    float gat = (att == 0.f) ? 1.f : att;
    float scale = cnt / (gat * fmaxf(cnt, 1.f));
    g_gx[g * 64 + tid] = acc * scale;
}

// ---------------- final MLP: out = relu(gx@fc1+b)@fc2+b ----------------
__global__ void k_mlp(const float* __restrict__ f1w, const float* __restrict__ f1b,
                      const float* __restrict__ f2w, const float* __restrict__ f2b,
                      float* __restrict__ out) {
    int g = blockIdx.x, tid = threadIdx.x;  // 128 threads
    __shared__ float sx[64];
    __shared__ float shh[128];
    if (tid < 64) sx[tid] = g_gx[g * 64 + tid];
    __syncthreads();
    float a = f1b[tid];
#pragma unroll 8
    for (int k = 0; k < 64; k++) a = fmaf(sx[k], f1w[k * 128 + tid], a);
    shh[tid] = fmaxf(a, 0.f);
    __syncthreads();
    if (tid < 3) {
        float o = f2b[tid];
        for (int j = 0; j < 128; j++) o = fmaf(shh[j], f2w[j * 3 + tid], o);
        out[g * 3 + tid] = o;
    }
}

// ---------------- launch ----------------
extern "C" void kernel_launch(void* const* d_in, const int* in_sizes, int n_in,
                              void* d_out, int out_size) {
    const float* x     = (const float*)d_in[0];
    const int*   ei    = (const int*)d_in[1];
    const int*   batch = (const int*)d_in[2];
    const float* eattr = (const float*)d_in[3];
    const float* eatt  = (const float*)d_in[4];
    const float* embw  = (const float*)d_in[5];
    const float* embb  = (const float*)d_in[6];
    const float* l1w   = (const float*)d_in[7];
    const float* l1b   = (const float*)d_in[8];
    const float* l2w   = (const float*)d_in[9];
    const float* l3w   = (const float*)d_in[10];
    const float* l3b   = (const float*)d_in[11];
    const float* f1w   = (const float*)d_in[12];
    const float* f1b   = (const float*)d_in[13];
    const float* f2w   = (const float*)d_in[14];
    const float* f2b   = (const float*)d_in[15];
    float* out = (float*)d_out;

    const int smem_gemm = (128 * 68 + 64 * 64) * 4;  // 51200 B
    cudaFuncSetAttribute(k_gemm, cudaFuncAttributeMaxDynamicSharedMemorySize, smem_gemm);

    const int* src = ei;
    const int* dst = ei + NE;

    k_zero<<<(NN + 255) / 256, 256>>>();
    k_embed<<<(NN * 64 + 255) / 256, 256>>>(x, embw, embb);
    k_edge<<<(NE + 255) / 256, 256>>>(src, dst, eattr, eatt);

    int nscan = (NN + 1023) / 1024;  // 98
    k_scan1<<<nscan, 256>>>();
    k_scan2<<<1, 128>>>(nscan);
    k_scan3<<<(NN + 255) / 256, 256>>>();
    k_fill<<<(NE + 255) / 256, 256>>>(src, dst);

    for (int l = 0; l < 3; l++) {
        k_gemm<<<(NN + 127) / 128, 256, smem_gemm>>>(
            l1w + l * 4096, l2w + l * 4096, l3w + l * 4096,
            l1b + l * 64, l3b + l * 64);
        k_gather<<<(NN * 32 + 255) / 256, 256>>>();
    }

    k_pool<<<NGR, 64>>>(batch);
    k_mlp<<<NGR, 128>>>(f1w, f1b, f2w, f2b, out);
}

// round 2
// speedup vs baseline: 1.2332x; 1.2332x over previous
#include <cuda_runtime.h>

#define NN 100000
#define NE 1000000
#define NGR 512

// ---------------- scratch ----------------
__device__ float g_Win[NN];       // sum of incoming edge weights (row sums)
__device__ float g_atts[NN];      // attention sum: src-side atomic part, then total
__device__ int   g_degs[NN];      // src-side degree (atomic)
__device__ float g_natt[NN];      // final node attention
__device__ int   g_cnt[NN];       // in-degree (CSR row counts)
__device__ int   g_rs[NN];        // CSR row start
__device__ int   g_cur[NN];       // CSR fill cursor
__device__ int   g_bsum[128];     // scan block sums
__device__ float2 g_ce[NE];       // CSR: {src_as_float_bits, w}
__device__ float g_catt[NE];      // CSR: atten per slot
__device__ float g_h[NN * 64];
__device__ float g_A[NN * 64];
__device__ float g_D[NN * 64];
__device__ float g_gx[NGR * 64];

// ---------------- zero init ----------------
__global__ void k_zero() {
    int i = blockIdx.x * 256 + threadIdx.x;
    if (i < NN) { g_atts[i] = 0.f; g_degs[i] = 0; g_cnt[i] = 0; }
}

// ---------------- node embedding: h = x @ W(4x64) + b ----------------
__global__ void k_embed(const float* __restrict__ x, const float* __restrict__ w,
                        const float* __restrict__ b) {
    int gid = blockIdx.x * 256 + threadIdx.x;
    if (gid >= NN * 64) return;
    int i = gid >> 6, c = gid & 63;
    float x0 = x[i * 4], x1 = x[i * 4 + 1], x2 = x[i * 4 + 2], x3 = x[i * 4 + 3];
    g_h[gid] = b[c] + x0 * w[c] + x1 * w[64 + c] + x2 * w[128 + c] + x3 * w[192 + c];
}

// ---------------- edge pass: 3 atomics/edge, x4 vectorized ----------------
__global__ void k_edge(const int* __restrict__ src, const int* __restrict__ dst,
                       const float* __restrict__ atten) {
    int e4 = blockIdx.x * 256 + threadIdx.x;
    if (e4 * 4 >= NE) return;
    int4 s = *(const int4*)&src[e4 * 4];
    int4 d = *(const int4*)&dst[e4 * 4];
    float4 at = *(const float4*)&atten[e4 * 4];
    atomicAdd(&g_cnt[d.x], 1); atomicAdd(&g_cnt[d.y], 1);
    atomicAdd(&g_cnt[d.z], 1); atomicAdd(&g_cnt[d.w], 1);
    atomicAdd(&g_atts[s.x], at.x); atomicAdd(&g_atts[s.y], at.y);
    atomicAdd(&g_atts[s.z], at.z); atomicAdd(&g_atts[s.w], at.w);
    atomicAdd(&g_degs[s.x], 1); atomicAdd(&g_degs[s.y], 1);
    atomicAdd(&g_degs[s.z], 1); atomicAdd(&g_degs[s.w], 1);
}

// ---------------- exclusive scan of g_cnt -> g_rs ----------------
__global__ void k_scan1() {
    int tid = threadIdx.x;
    int base = blockIdx.x * 1024 + tid * 4;
    int v0 = 0, v1 = 0, v2 = 0, v3 = 0;
    if (base + 3 < NN) {
        int4 t = *(const int4*)&g_cnt[base];
        v0 = t.x; v1 = t.y; v2 = t.z; v3 = t.w;
    } else {
        if (base < NN)     v0 = g_cnt[base];
        if (base + 1 < NN) v1 = g_cnt[base + 1];
        if (base + 2 < NN) v2 = g_cnt[base + 2];
        if (base + 3 < NN) v3 = g_cnt[base + 3];
    }
    int sloc = v0 + v1 + v2 + v3;
    int x = sloc;
#pragma unroll
    for (int o = 1; o < 32; o <<= 1) {
        int y = __shfl_up_sync(0xffffffffu, x, o);
        if ((tid & 31) >= o) x += y;
    }
    __shared__ int wsum[8];
    if ((tid & 31) == 31) wsum[tid >> 5] = x;
    __syncthreads();
    if (tid < 8) {
        int y = wsum[tid];
#pragma unroll
        for (int o = 1; o < 8; o <<= 1) {
            int z = __shfl_up_sync(0xffu, y, o);
            if (tid >= o) y += z;
        }
        wsum[tid] = y;
    }
    __syncthreads();
    int woff = (tid >= 32) ? wsum[(tid >> 5) - 1] : 0;
    int excl = x - sloc + woff;
    if (base < NN)     g_rs[base]     = excl;
    if (base + 1 < NN) g_rs[base + 1] = excl + v0;
    if (base + 2 < NN) g_rs[base + 2] = excl + v0 + v1;
    if (base + 3 < NN) g_rs[base + 3] = excl + v0 + v1 + v2;
    if (tid == 255) g_bsum[blockIdx.x] = excl + sloc;
}

__global__ void k_scan2(int nb) {
    int tid = threadIdx.x;  // 128
    int v = (tid < nb) ? g_bsum[tid] : 0;
    int x = v;
#pragma unroll
    for (int o = 1; o < 32; o <<= 1) {
        int y = __shfl_up_sync(0xffffffffu, x, o);
        if ((tid & 31) >= o) x += y;
    }
    __shared__ int ws[4];
    if ((tid & 31) == 31) ws[tid >> 5] = x;
    __syncthreads();
    int add = 0;
    for (int wq = 0; wq < (tid >> 5); wq++) add += ws[wq];
    x += add;
    if (tid < nb) g_bsum[tid] = x - v;
}

__global__ void k_scan3() {
    int i = blockIdx.x * 256 + threadIdx.x;
    if (i < NN) {
        int r = g_rs[i] + g_bsum[i >> 10];
        g_rs[i] = r;
        g_cur[i] = r;
    }
}

// ---------------- CSR fill (x2 vectorized loads) ----------------
__global__ void k_fill(const int* __restrict__ src, const int* __restrict__ dst,
                       const float* __restrict__ attr, const float* __restrict__ atten) {
    int e2 = blockIdx.x * 256 + threadIdx.x;
    if (e2 * 2 >= NE) return;
    int2 s = *(const int2*)&src[e2 * 2];
    int2 d = *(const int2*)&dst[e2 * 2];
    float2 ar = *(const float2*)&attr[e2 * 2];
    float2 at = *(const float2*)&atten[e2 * 2];
    int p0 = atomicAdd(&g_cur[d.x], 1);
    g_ce[p0] = make_float2(__int_as_float(s.x), ar.x * at.x);
    g_catt[p0] = at.x;
    int p1 = atomicAdd(&g_cur[d.y], 1);
    g_ce[p1] = make_float2(__int_as_float(s.y), ar.y * at.y);
    g_catt[p1] = at.y;
}

// ---------------- row stats: Win, total atts, node_att (warp per node) ------
__global__ void k_rowstats() {
    int gt = blockIdx.x * 256 + threadIdx.x;
    int node = gt >> 5, lane = gt & 31;
    if (node >= NN) return;
    int s = g_rs[node];
    int len = g_cnt[node];
    float wsum = 0.f, asum = 0.f;
    for (int i = lane; i < len; i += 32) {
        wsum += g_ce[s + i].y;
        asum += g_catt[s + i];
    }
#pragma unroll
    for (int o = 16; o > 0; o >>= 1) {
        wsum += __shfl_down_sync(0xffffffffu, wsum, o);
        asum += __shfl_down_sync(0xffffffffu, asum, o);
    }
    if (lane == 0) {
        g_Win[node] = wsum;
        float att_tot = asum + g_atts[node];
        float deg = (float)(len + g_degs[node]);
        g_natt[node] = att_tot / ((deg == 0.f) ? 1.f : deg);
    }
}

// ---------------- layer GEMM: single pass over h, 3 weight mats ----------------
// A = h@W1+b1 ; D = h@W3+b3 - Win*(h@W2)
__global__ void __launch_bounds__(256, 2) k_gemm(const float* __restrict__ W1,
                                                 const float* __restrict__ W2,
                                                 const float* __restrict__ W3,
                                                 const float* __restrict__ b1,
                                                 const float* __restrict__ b3) {
    extern __shared__ float sm[];
    float* sh_h = sm;              // [128][65] stride-65, conflict-free
    float* sh_w = sm + 128 * 65;   // [3][64][64]
    int tid = threadIdx.x;
    int nb = blockIdx.x * 128;

    // load h tile (coalesced float4 read, 4 scalar STS at stride 65)
    for (int i = tid; i < 2048; i += 256) {
        int node = i >> 4, k4 = (i & 15) << 2;
        float4 v = make_float4(0.f, 0.f, 0.f, 0.f);
        int gn = nb + node;
        if (gn < NN) v = *(const float4*)&g_h[gn * 64 + k4];
        float* p = &sh_h[node * 65 + k4];
        p[0] = v.x; p[1] = v.y; p[2] = v.z; p[3] = v.w;
    }
    // load 3 weight matrices
    for (int i = tid; i < 1024; i += 256) {
        ((float4*)sh_w)[i]        = ((const float4*)W1)[i];
        ((float4*)sh_w)[1024 + i] = ((const float4*)W2)[i];
        ((float4*)sh_w)[2048 + i] = ((const float4*)W3)[i];
    }
    __syncthreads();

    int c4 = (tid & 15) << 2;
    int r0 = (tid >> 4) << 3;
    float4 acc0[8], acc1[8], acc2[8];
#pragma unroll
    for (int j = 0; j < 8; j++) {
        acc0[j] = make_float4(0.f, 0.f, 0.f, 0.f);
        acc1[j] = make_float4(0.f, 0.f, 0.f, 0.f);
        acc2[j] = make_float4(0.f, 0.f, 0.f, 0.f);
    }

#pragma unroll 2
    for (int k = 0; k < 64; k++) {
        float4 w0 = *(const float4*)&sh_w[k * 64 + c4];
        float4 w1 = *(const float4*)&sh_w[4096 + k * 64 + c4];
        float4 w2 = *(const float4*)&sh_w[8192 + k * 64 + c4];
#pragma unroll
        for (int j = 0; j < 8; j++) {
            float hv = sh_h[(r0 + j) * 65 + k];
            acc0[j].x = fmaf(hv, w0.x, acc0[j].x);
            acc0[j].y = fmaf(hv, w0.y, acc0[j].y);
            acc0[j].z = fmaf(hv, w0.z, acc0[j].z);
            acc0[j].w = fmaf(hv, w0.w, acc0[j].w);
            acc1[j].x = fmaf(hv, w1.x, acc1[j].x);
            acc1[j].y = fmaf(hv, w1.y, acc1[j].y);
            acc1[j].z = fmaf(hv, w1.z, acc1[j].z);
            acc1[j].w = fmaf(hv, w1.w, acc1[j].w);
            acc2[j].x = fmaf(hv, w2.x, acc2[j].x);
            acc2[j].y = fmaf(hv, w2.y, acc2[j].y);
            acc2[j].z = fmaf(hv, w2.z, acc2[j].z);
            acc2[j].w = fmaf(hv, w2.w, acc2[j].w);
        }
    }

    float4 b1v = *(const float4*)&b1[c4];
    float4 b3v = *(const float4*)&b3[c4];
#pragma unroll
    for (int j = 0; j < 8; j++) {
        int gn = nb + r0 + j;
        if (gn < NN) {
            float4 oa = make_float4(acc0[j].x + b1v.x, acc0[j].y + b1v.y,
                                    acc0[j].z + b1v.z, acc0[j].w + b1v.w);
            *(float4*)&g_A[gn * 64 + c4] = oa;
            float win = g_Win[gn];
            float4 od = make_float4(acc2[j].x + b3v.x - win * acc1[j].x,
                                    acc2[j].y + b3v.y - win * acc1[j].y,
                                    acc2[j].z + b3v.z - win * acc1[j].z,
                                    acc2[j].w + b3v.w - win * acc1[j].w);
            *(float4*)&g_D[gn * 64 + c4] = od;
        }
    }
}

// ---------------- gather: h = relu( sum_e w*A[src] + D ), warp per node ----------------
__global__ void k_gather() {
    int gt = blockIdx.x * 256 + threadIdx.x;
    int node = gt >> 5, lane = gt & 31;
    if (node >= NN) return;
    int s = g_rs[node];
    int e = s + g_cnt[node];
    float ax = 0.f, ay = 0.f;
    for (int base = s; base < e; base += 32) {
        int idx = base + lane;
        float2 ce = make_float2(0.f, 0.f);
        if (idx < e) ce = g_ce[idx];
        int sn = __float_as_int(ce.x);
        float wv = ce.y;
        int m = min(32, e - base);
        for (int j = 0; j < m; j++) {
            int ss = __shfl_sync(0xffffffffu, sn, j);
            float ww = __shfl_sync(0xffffffffu, wv, j);
            float2 av = *(const float2*)&g_A[ss * 64 + lane * 2];
            ax = fmaf(ww, av.x, ax);
            ay = fmaf(ww, av.y, ay);
        }
    }
    float2 dv = *(const float2*)&g_D[node * 64 + lane * 2];
    float2 hv = make_float2(fmaxf(ax + dv.x, 0.f), fmaxf(ay + dv.y, 0.f));
    *(float2*)&g_h[node * 64 + lane * 2] = hv;
}

// ---------------- pooling (batch sorted -> binary search) ----------------
__global__ void k_pool(const int* __restrict__ batch) {
    int g = blockIdx.x, tid = threadIdx.x;  // 64 threads
    __shared__ int se[2];
    if (tid < 2) {
        int key = g + tid;
        int lo = 0, hi = NN;
        while (lo < hi) {
            int mid = (lo + hi) >> 1;
            if (batch[mid] < key) lo = mid + 1; else hi = mid;
        }
        se[tid] = lo;
    }
    __syncthreads();
    int s = se[0], e = se[1];
    float acc = 0.f, att = 0.f;
    for (int i = s; i < e; i++) {
        float na = g_natt[i];
        acc = fmaf(g_h[i * 64 + tid], na, acc);
        att += na;
    }
    float cnt = (float)(e - s);
    float gat = (att == 0.f) ? 1.f : att;
    float scale = cnt / (gat * fmaxf(cnt, 1.f));
    g_gx[g * 64 + tid] = acc * scale;
}

// ---------------- final MLP ----------------
__global__ void k_mlp(const float* __restrict__ f1w, const float* __restrict__ f1b,
                      const float* __restrict__ f2w, const float* __restrict__ f2b,
                      float* __restrict__ out) {
    int g = blockIdx.x, tid = threadIdx.x;  // 128
    __shared__ float sx[64];
    __shared__ float shh[128];
    if (tid < 64) sx[tid] = g_gx[g * 64 + tid];
    __syncthreads();
    float a = f1b[tid];
#pragma unroll 8
    for (int k = 0; k < 64; k++) a = fmaf(sx[k], f1w[k * 128 + tid], a);
    shh[tid] = fmaxf(a, 0.f);
    __syncthreads();
    if (tid < 3) {
        float o = f2b[tid];
        for (int j = 0; j < 128; j++) o = fmaf(shh[j], f2w[j * 3 + tid], o);
        out[g * 3 + tid] = o;
    }
}

// ---------------- launch ----------------
extern "C" void kernel_launch(void* const* d_in, const int* in_sizes, int n_in,
                              void* d_out, int out_size) {
    const float* x     = (const float*)d_in[0];
    const int*   ei    = (const int*)d_in[1];
    const int*   batch = (const int*)d_in[2];
    const float* eattr = (const float*)d_in[3];
    const float* eatt  = (const float*)d_in[4];
    const float* embw  = (const float*)d_in[5];
    const float* embb  = (const float*)d_in[6];
    const float* l1w   = (const float*)d_in[7];
    const float* l1b   = (const float*)d_in[8];
    const float* l2w   = (const float*)d_in[9];
    const float* l3w   = (const float*)d_in[10];
    const float* l3b   = (const float*)d_in[11];
    const float* f1w   = (const float*)d_in[12];
    const float* f1b   = (const float*)d_in[13];
    const float* f2w   = (const float*)d_in[14];
    const float* f2b   = (const float*)d_in[15];
    float* out = (float*)d_out;

    const int smem_gemm = (128 * 65 + 3 * 4096) * 4;  // 81920 B
    cudaFuncSetAttribute(k_gemm, cudaFuncAttributeMaxDynamicSharedMemorySize, smem_gemm);

    const int* src = ei;
    const int* dst = ei + NE;

    k_zero<<<(NN + 255) / 256, 256>>>();
    k_embed<<<(NN * 64 + 255) / 256, 256>>>(x, embw, embb);
    k_edge<<<(NE / 4 + 255) / 256, 256>>>(src, dst, eatt);

    int nscan = (NN + 1023) / 1024;  // 98
    k_scan1<<<nscan, 256>>>();
    k_scan2<<<1, 128>>>(nscan);
    k_scan3<<<(NN + 255) / 256, 256>>>();
    k_fill<<<(NE / 2 + 255) / 256, 256>>>(src, dst, eattr, eatt);
    k_rowstats<<<(NN * 32 + 255) / 256, 256>>>();

    for (int l = 0; l < 3; l++) {
        k_gemm<<<(NN + 127) / 128, 256, smem_gemm>>>(
            l1w + l * 4096, l2w + l * 4096, l3w + l * 4096,
            l1b + l * 64, l3b + l * 64);
        k_gather<<<(NN * 32 + 255) / 256, 256>>>();
    }

    k_pool<<<NGR, 64>>>(batch);
    k_mlp<<<NGR, 128>>>(f1w, f1b, f2w, f2b, out);
}

// round 3
// speedup vs baseline: 1.3614x; 1.1040x over previous
#include <cuda_runtime.h>
#include <cstdint>

#define NN 100000
#define NE 1000000
#define NGR 512

// ---------------- scratch ----------------
__device__ float g_Win[NN];
__device__ float g_atts[NN];
__device__ int   g_degs[NN];
__device__ float g_natt[NN];
__device__ int   g_cnt[NN];
__device__ int   g_rs[NN];
__device__ int   g_cur[NN];
__device__ int   g_bsum[128];
__device__ float2 g_ce[NE];       // CSR: {src_as_bits, w}
__device__ float g_catt[NE];
__device__ float g_h[NN * 64];
__device__ float g_A[NN * 64];
__device__ float g_D[NN * 64];
__device__ float g_gx[NGR * 64];

__device__ __forceinline__ uint32_t f2tf32(float f) {
    uint32_t o;
    asm("cvt.rna.tf32.f32 %0, %1;" : "=r"(o) : "f"(f));
    return o;
}

// ---------------- zero init ----------------
__global__ void k_zero() {
    int i = blockIdx.x * 256 + threadIdx.x;
    if (i < NN) { g_atts[i] = 0.f; g_degs[i] = 0; g_cnt[i] = 0; }
}

// ---------------- node embedding ----------------
__global__ void k_embed(const float* __restrict__ x, const float* __restrict__ w,
                        const float* __restrict__ b) {
    int gid = blockIdx.x * 256 + threadIdx.x;
    if (gid >= NN * 64) return;
    int i = gid >> 6, c = gid & 63;
    float x0 = x[i * 4], x1 = x[i * 4 + 1], x2 = x[i * 4 + 2], x3 = x[i * 4 + 3];
    g_h[gid] = b[c] + x0 * w[c] + x1 * w[64 + c] + x2 * w[128 + c] + x3 * w[192 + c];
}

// ---------------- edge pass ----------------
__global__ void k_edge(const int* __restrict__ src, const int* __restrict__ dst,
                       const float* __restrict__ atten) {
    int e4 = blockIdx.x * 256 + threadIdx.x;
    if (e4 * 4 >= NE) return;
    int4 s = *(const int4*)&src[e4 * 4];
    int4 d = *(const int4*)&dst[e4 * 4];
    float4 at = *(const float4*)&atten[e4 * 4];
    atomicAdd(&g_cnt[d.x], 1); atomicAdd(&g_cnt[d.y], 1);
    atomicAdd(&g_cnt[d.z], 1); atomicAdd(&g_cnt[d.w], 1);
    atomicAdd(&g_atts[s.x], at.x); atomicAdd(&g_atts[s.y], at.y);
    atomicAdd(&g_atts[s.z], at.z); atomicAdd(&g_atts[s.w], at.w);
    atomicAdd(&g_degs[s.x], 1); atomicAdd(&g_degs[s.y], 1);
    atomicAdd(&g_degs[s.z], 1); atomicAdd(&g_degs[s.w], 1);
}

// ---------------- exclusive scan ----------------
__global__ void k_scan1() {
    int tid = threadIdx.x;
    int base = blockIdx.x * 1024 + tid * 4;
    int v0 = 0, v1 = 0, v2 = 0, v3 = 0;
    if (base + 3 < NN) {
        int4 t = *(const int4*)&g_cnt[base];
        v0 = t.x; v1 = t.y; v2 = t.z; v3 = t.w;
    } else {
        if (base < NN)     v0 = g_cnt[base];
        if (base + 1 < NN) v1 = g_cnt[base + 1];
        if (base + 2 < NN) v2 = g_cnt[base + 2];
        if (base + 3 < NN) v3 = g_cnt[base + 3];
    }
    int sloc = v0 + v1 + v2 + v3;
    int x = sloc;
#pragma unroll
    for (int o = 1; o < 32; o <<= 1) {
        int y = __shfl_up_sync(0xffffffffu, x, o);
        if ((tid & 31) >= o) x += y;
    }
    __shared__ int wsum[8];
    if ((tid & 31) == 31) wsum[tid >> 5] = x;
    __syncthreads();
    if (tid < 8) {
        int y = wsum[tid];
#pragma unroll
        for (int o = 1; o < 8; o <<= 1) {
            int z = __shfl_up_sync(0xffu, y, o);
            if (tid >= o) y += z;
        }
        wsum[tid] = y;
    }
    __syncthreads();
    int woff = (tid >= 32) ? wsum[(tid >> 5) - 1] : 0;
    int excl = x - sloc + woff;
    if (base < NN)     g_rs[base]     = excl;
    if (base + 1 < NN) g_rs[base + 1] = excl + v0;
    if (base + 2 < NN) g_rs[base + 2] = excl + v0 + v1;
    if (base + 3 < NN) g_rs[base + 3] = excl + v0 + v1 + v2;
    if (tid == 255) g_bsum[blockIdx.x] = excl + sloc;
}

__global__ void k_scan2(int nb) {
    int tid = threadIdx.x;
    int v = (tid < nb) ? g_bsum[tid] : 0;
    int x = v;
#pragma unroll
    for (int o = 1; o < 32; o <<= 1) {
        int y = __shfl_up_sync(0xffffffffu, x, o);
        if ((tid & 31) >= o) x += y;
    }
    __shared__ int ws[4];
    if ((tid & 31) == 31) ws[tid >> 5] = x;
    __syncthreads();
    int add = 0;
    for (int wq = 0; wq < (tid >> 5); wq++) add += ws[wq];
    x += add;
    if (tid < nb) g_bsum[tid] = x - v;
}

__global__ void k_scan3() {
    int i = blockIdx.x * 256 + threadIdx.x;
    if (i < NN) {
        int r = g_rs[i] + g_bsum[i >> 10];
        g_rs[i] = r;
        g_cur[i] = r;
    }
}

// ---------------- CSR fill ----------------
__global__ void k_fill(const int* __restrict__ src, const int* __restrict__ dst,
                       const float* __restrict__ attr, const float* __restrict__ atten) {
    int e2 = blockIdx.x * 256 + threadIdx.x;
    if (e2 * 2 >= NE) return;
    int2 s = *(const int2*)&src[e2 * 2];
    int2 d = *(const int2*)&dst[e2 * 2];
    float2 ar = *(const float2*)&attr[e2 * 2];
    float2 at = *(const float2*)&atten[e2 * 2];
    int p0 = atomicAdd(&g_cur[d.x], 1);
    g_ce[p0] = make_float2(__int_as_float(s.x), ar.x * at.x);
    g_catt[p0] = at.x;
    int p1 = atomicAdd(&g_cur[d.y], 1);
    g_ce[p1] = make_float2(__int_as_float(s.y), ar.y * at.y);
    g_catt[p1] = at.y;
}

// ---------------- row stats ----------------
__global__ void k_rowstats() {
    int gt = blockIdx.x * 256 + threadIdx.x;
    int node = gt >> 5, lane = gt & 31;
    if (node >= NN) return;
    int s = g_rs[node];
    int len = g_cnt[node];
    float wsum = 0.f, asum = 0.f;
    for (int i = lane; i < len; i += 32) {
        wsum += g_ce[s + i].y;
        asum += g_catt[s + i];
    }
#pragma unroll
    for (int o = 16; o > 0; o >>= 1) {
        wsum += __shfl_down_sync(0xffffffffu, wsum, o);
        asum += __shfl_down_sync(0xffffffffu, asum, o);
    }
    if (lane == 0) {
        g_Win[node] = wsum;
        float att_tot = asum + g_atts[node];
        float deg = (float)(len + g_degs[node]);
        g_natt[node] = att_tot / ((deg == 0.f) ? 1.f : deg);
    }
}

// ---------------- layer GEMM via mma.sync tf32 ----------------
// 512 threads, 16 warps: rowWarp = w&7 (16 rows each), colHalf = w>>3 (32 cols
// of each of W1,W2,W3). h tile [128][68] tf32, W tile [64][200] tf32.
// A = h@W1+b1 ; D = h@W3+b3 - Win*(h@W2)
__global__ void __launch_bounds__(512) k_gemm(const float* __restrict__ W1,
                                              const float* __restrict__ W2,
                                              const float* __restrict__ W3,
                                              const float* __restrict__ b1,
                                              const float* __restrict__ b3) {
    extern __shared__ float sm[];
    float* sh_h = sm;              // [128][68]
    float* sh_w = sm + 128 * 68;   // [64][200], cols 0..191 used
    int tid = threadIdx.x;
    int nbase = blockIdx.x * 128;

    // h tile -> smem (tf32-rounded)
    for (int i = tid; i < 2048; i += 512) {
        int node = i >> 4, k4 = (i & 15) << 2;
        float4 v = make_float4(0.f, 0.f, 0.f, 0.f);
        int gn = nbase + node;
        if (gn < NN) v = *(const float4*)&g_h[gn * 64 + k4];
        uint32_t r0 = f2tf32(v.x), r1 = f2tf32(v.y), r2 = f2tf32(v.z), r3 = f2tf32(v.w);
        uint32_t* p = (uint32_t*)&sh_h[node * 68 + k4];
        p[0] = r0; p[1] = r1; p[2] = r2; p[3] = r3;
    }
    // W1|W2|W3 -> smem stride 200 (tf32-rounded)
    for (int i = tid; i < 3072; i += 512) {
        int row = i / 16;            // 0..191 over (mat,16 float4 per row)? no:
        // i indexes [64 rows][48 float4]: row = i/48, q = i%48
        row = i / 48;
        int q = i % 48;
        int m = q >> 4, c4 = (q & 15) << 2;
        const float* Wm = (m == 0) ? W1 : ((m == 1) ? W2 : W3);
        float4 v = *(const float4*)&Wm[row * 64 + c4];
        uint32_t* p = (uint32_t*)&sh_w[row * 200 + m * 64 + c4];
        p[0] = f2tf32(v.x); p[1] = f2tf32(v.y); p[2] = f2tf32(v.z); p[3] = f2tf32(v.w);
    }
    __syncthreads();

    int w = tid >> 5, lane = tid & 31;
    int rowW = w & 7, colH = w >> 3;
    int gid = lane >> 2, tid4 = lane & 3;

    float acc[12][4];
#pragma unroll
    for (int t = 0; t < 12; t++) {
        acc[t][0] = 0.f; acc[t][1] = 0.f; acc[t][2] = 0.f; acc[t][3] = 0.f;
    }

    const uint32_t* hp = (const uint32_t*)(sh_h + rowW * 16 * 68);
    const uint32_t* wp = (const uint32_t*)sh_w;

#pragma unroll
    for (int kt = 0; kt < 8; kt++) {
        int k0 = kt * 8;
        uint32_t a0 = hp[gid * 68 + k0 + tid4];
        uint32_t a1 = hp[(gid + 8) * 68 + k0 + tid4];
        uint32_t a2 = hp[gid * 68 + k0 + tid4 + 4];
        uint32_t a3 = hp[(gid + 8) * 68 + k0 + tid4 + 4];
#pragma unroll
        for (int m = 0; m < 3; m++) {
#pragma unroll
            for (int tt = 0; tt < 4; tt++) {
                int nb = m * 64 + colH * 32 + tt * 8;
                uint32_t bb0 = wp[(k0 + tid4) * 200 + nb + gid];
                uint32_t bb1 = wp[(k0 + tid4 + 4) * 200 + nb + gid];
                float* c = acc[m * 4 + tt];
                asm volatile(
                    "mma.sync.aligned.m16n8k8.row.col.f32.tf32.tf32.f32 "
                    "{%0,%1,%2,%3}, {%4,%5,%6,%7}, {%8,%9}, {%0,%1,%2,%3};"
                    : "+f"(c[0]), "+f"(c[1]), "+f"(c[2]), "+f"(c[3])
                    : "r"(a0), "r"(a1), "r"(a2), "r"(a3), "r"(bb0), "r"(bb1));
            }
        }
    }

    // epilogue
    int r1 = nbase + rowW * 16 + gid;
    int r2 = r1 + 8;
    float win1 = (r1 < NN) ? g_Win[r1] : 0.f;
    float win2 = (r2 < NN) ? g_Win[r2] : 0.f;
#pragma unroll
    for (int tt = 0; tt < 4; tt++) {
        int c = colH * 32 + tt * 8 + tid4 * 2;
        float2 b1v = *(const float2*)&b1[c];
        float2 b3v = *(const float2*)&b3[c];
        float* aW1 = acc[tt];
        float* aW2 = acc[4 + tt];
        float* aW3 = acc[8 + tt];
        if (r1 < NN) {
            *(float2*)&g_A[r1 * 64 + c] = make_float2(aW1[0] + b1v.x, aW1[1] + b1v.y);
            *(float2*)&g_D[r1 * 64 + c] = make_float2(aW3[0] + b3v.x - win1 * aW2[0],
                                                      aW3[1] + b3v.y - win1 * aW2[1]);
        }
        if (r2 < NN) {
            *(float2*)&g_A[r2 * 64 + c] = make_float2(aW1[2] + b1v.x, aW1[3] + b1v.y);
            *(float2*)&g_D[r2 * 64 + c] = make_float2(aW3[2] + b3v.x - win2 * aW2[2],
                                                      aW3[3] + b3v.y - win2 * aW2[3]);
        }
    }
}

// ---------------- gather: h = relu( sum_e w*A[src] + D ), warp per node ----------------
__global__ void k_gather() {
    int gt = blockIdx.x * 256 + threadIdx.x;
    int node = gt >> 5, lane = gt & 31;
    if (node >= NN) return;
    int s = g_rs[node];
    int e = s + g_cnt[node];
    float ax0 = 0.f, ay0 = 0.f, ax1 = 0.f, ay1 = 0.f;
    for (int base = s; base < e; base += 32) {
        int idx = base + lane;
        float2 ce = make_float2(0.f, 0.f);
        if (idx < e) ce = g_ce[idx];
        int sn = __float_as_int(ce.x);
        float wv = ce.y;
        int m = min(32, e - base);
        int mr = (m + 3) & ~3;
        for (int j = 0; j < mr; j += 4) {
            int s0 = __shfl_sync(0xffffffffu, sn, j);
            int s1 = __shfl_sync(0xffffffffu, sn, j + 1);
            int s2 = __shfl_sync(0xffffffffu, sn, j + 2);
            int s3 = __shfl_sync(0xffffffffu, sn, j + 3);
            float w0 = __shfl_sync(0xffffffffu, wv, j);
            float w1 = __shfl_sync(0xffffffffu, wv, j + 1);
            float w2 = __shfl_sync(0xffffffffu, wv, j + 2);
            float w3 = __shfl_sync(0xffffffffu, wv, j + 3);
            float2 v0 = *(const float2*)&g_A[s0 * 64 + lane * 2];
            float2 v1 = *(const float2*)&g_A[s1 * 64 + lane * 2];
            float2 v2 = *(const float2*)&g_A[s2 * 64 + lane * 2];
            float2 v3 = *(const float2*)&g_A[s3 * 64 + lane * 2];
            ax0 = fmaf(w0, v0.x, ax0); ay0 = fmaf(w0, v0.y, ay0);
            ax1 = fmaf(w1, v1.x, ax1); ay1 = fmaf(w1, v1.y, ay1);
            ax0 = fmaf(w2, v2.x, ax0); ay0 = fmaf(w2, v2.y, ay0);
            ax1 = fmaf(w3, v3.x, ax1); ay1 = fmaf(w3, v3.y, ay1);
        }
    }
    float2 dv = *(const float2*)&g_D[node * 64 + lane * 2];
    float2 hv = make_float2(fmaxf(ax0 + ax1 + dv.x, 0.f), fmaxf(ay0 + ay1 + dv.y, 0.f));
    *(float2*)&g_h[node * 64 + lane * 2] = hv;
}

// ---------------- pooling ----------------
__global__ void k_pool(const int* __restrict__ batch) {
    int g = blockIdx.x, tid = threadIdx.x;  // 64 threads
    __shared__ int se[2];
    if (tid < 2) {
        int key = g + tid;
        int lo = 0, hi = NN;
        while (lo < hi) {
            int mid = (lo + hi) >> 1;
            if (batch[mid] < key) lo = mid + 1; else hi = mid;
        }
        se[tid] = lo;
    }
    __syncthreads();
    int s = se[0], e = se[1];
    float acc = 0.f, att = 0.f;
    for (int i = s; i < e; i++) {
        float na = g_natt[i];
        acc = fmaf(g_h[i * 64 + tid], na, acc);
        att += na;
    }
    float cnt = (float)(e - s);
    float gat = (att == 0.f) ? 1.f : att;
    float scale = cnt / (gat * fmaxf(cnt, 1.f));
    g_gx[g * 64 + tid] = acc * scale;
}

// ---------------- final MLP ----------------
__global__ void k_mlp(const float* __restrict__ f1w, const float* __restrict__ f1b,
                      const float* __restrict__ f2w, const float* __restrict__ f2b,
                      float* __restrict__ out) {
    int g = blockIdx.x, tid = threadIdx.x;  // 128
    __shared__ float sx[64];
    __shared__ float shh[128];
    if (tid < 64) sx[tid] = g_gx[g * 64 + tid];
    __syncthreads();
    float a = f1b[tid];
#pragma unroll 8
    for (int k = 0; k < 64; k++) a = fmaf(sx[k], f1w[k * 128 + tid], a);
    shh[tid] = fmaxf(a, 0.f);
    __syncthreads();
    if (tid < 3) {
        float o = f2b[tid];
        for (int j = 0; j < 128; j++) o = fmaf(shh[j], f2w[j * 3 + tid], o);
        out[g * 3 + tid] = o;
    }
}

// ---------------- launch ----------------
extern "C" void kernel_launch(void* const* d_in, const int* in_sizes, int n_in,
                              void* d_out, int out_size) {
    const float* x     = (const float*)d_in[0];
    const int*   ei    = (const int*)d_in[1];
    const int*   batch = (const int*)d_in[2];
    const float* eattr = (const float*)d_in[3];
    const float* eatt  = (const float*)d_in[4];
    const float* embw  = (const float*)d_in[5];
    const float* embb  = (const float*)d_in[6];
    const float* l1w   = (const float*)d_in[7];
    const float* l1b   = (const float*)d_in[8];
    const float* l2w   = (const float*)d_in[9];
    const float* l3w   = (const float*)d_in[10];
    const float* l3b   = (const float*)d_in[11];
    const float* f1w   = (const float*)d_in[12];
    const float* f1b   = (const float*)d_in[13];
    const float* f2w   = (const float*)d_in[14];
    const float* f2b   = (const float*)d_in[15];
    float* out = (float*)d_out;

    const int smem_gemm = (128 * 68 + 64 * 200) * 4;  // 86016 B
    cudaFuncSetAttribute(k_gemm, cudaFuncAttributeMaxDynamicSharedMemorySize, smem_gemm);

    const int* src = ei;
    const int* dst = ei + NE;

    k_zero<<<(NN + 255) / 256, 256>>>();
    k_embed<<<(NN * 64 + 255) / 256, 256>>>(x, embw, embb);
    k_edge<<<(NE / 4 + 255) / 256, 256>>>(src, dst, eatt);

    int nscan = (NN + 1023) / 1024;  // 98
    k_scan1<<<nscan, 256>>>();
    k_scan2<<<1, 128>>>(nscan);
    k_scan3<<<(NN + 255) / 256, 256>>>();
    k_fill<<<(NE / 2 + 255) / 256, 256>>>(src, dst, eattr, eatt);
    k_rowstats<<<(NN * 32 + 255) / 256, 256>>>();

    for (int l = 0; l < 3; l++) {
        k_gemm<<<(NN + 127) / 128, 512, smem_gemm>>>(
            l1w + l * 4096, l2w + l * 4096, l3w + l * 4096,
            l1b + l * 64, l3b + l * 64);
        k_gather<<<(NN * 32 + 255) / 256, 256>>>();
    }

    k_pool<<<NGR, 64>>>(batch);
    k_mlp<<<NGR, 128>>>(f1w, f1b, f2w, f2b, out);
}

// round 5
// speedup vs baseline: 1.5686x; 1.1522x over previous
#include <cuda_runtime.h>
#include <cuda_fp16.h>
#include <cstdint>

#define NN 100000
#define NE 1000000
#define NGR 512

// ---------------- scratch ----------------
__device__ float g_Win[NN];
__device__ float g_atts[NN];
__device__ int   g_degs[NN];
__device__ float g_natt[NN];
__device__ int   g_cnt[NN];
__device__ int   g_rs[NN];
__device__ int   g_cur[NN];
__device__ int   g_bsum[128];
__device__ float2 g_ce[NE];       // CSR: {src_as_bits, w}
__device__ float g_catt[NE];
__device__ float g_h[NN * 64];
__device__ __half g_Ah[NN * 64];  // A in fp16 (gather-side)
__device__ float g_D[NN * 64];
__device__ float g_gx[NGR * 64];

__device__ __forceinline__ uint32_t f2tf32(float f) {
    uint32_t o;
    asm("cvt.rna.tf32.f32 %0, %1;" : "=r"(o) : "f"(f));
    return o;
}

// ---------------- init: zero + node embedding fused ----------------
__global__ void k_init(const float* __restrict__ x, const float* __restrict__ w,
                       const float* __restrict__ b) {
    int gid = blockIdx.x * 256 + threadIdx.x;
    if (gid < NN) { g_atts[gid] = 0.f; g_degs[gid] = 0; g_cnt[gid] = 0; }
    if (gid < NN * 64) {
        int i = gid >> 6, c = gid & 63;
        float x0 = x[i * 4], x1 = x[i * 4 + 1], x2 = x[i * 4 + 2], x3 = x[i * 4 + 3];
        g_h[gid] = b[c] + x0 * w[c] + x1 * w[64 + c] + x2 * w[128 + c] + x3 * w[192 + c];
    }
}

// ---------------- edge pass ----------------
__global__ void k_edge(const int* __restrict__ src, const int* __restrict__ dst,
                       const float* __restrict__ atten) {
    int e4 = blockIdx.x * 256 + threadIdx.x;
    if (e4 * 4 >= NE) return;
    int4 s = *(const int4*)&src[e4 * 4];
    int4 d = *(const int4*)&dst[e4 * 4];
    float4 at = *(const float4*)&atten[e4 * 4];
    atomicAdd(&g_cnt[d.x], 1); atomicAdd(&g_cnt[d.y], 1);
    atomicAdd(&g_cnt[d.z], 1); atomicAdd(&g_cnt[d.w], 1);
    atomicAdd(&g_atts[s.x], at.x); atomicAdd(&g_atts[s.y], at.y);
    atomicAdd(&g_atts[s.z], at.z); atomicAdd(&g_atts[s.w], at.w);
    atomicAdd(&g_degs[s.x], 1); atomicAdd(&g_degs[s.y], 1);
    atomicAdd(&g_degs[s.z], 1); atomicAdd(&g_degs[s.w], 1);
}

// ---------------- exclusive scan ----------------
__global__ void k_scan1() {
    int tid = threadIdx.x;
    int base = blockIdx.x * 1024 + tid * 4;
    int v0 = 0, v1 = 0, v2 = 0, v3 = 0;
    if (base + 3 < NN) {
        int4 t = *(const int4*)&g_cnt[base];
        v0 = t.x; v1 = t.y; v2 = t.z; v3 = t.w;
    } else {
        if (base < NN)     v0 = g_cnt[base];
        if (base + 1 < NN) v1 = g_cnt[base + 1];
        if (base + 2 < NN) v2 = g_cnt[base + 2];
        if (base + 3 < NN) v3 = g_cnt[base + 3];
    }
    int sloc = v0 + v1 + v2 + v3;
    int x = sloc;
#pragma unroll
    for (int o = 1; o < 32; o <<= 1) {
        int y = __shfl_up_sync(0xffffffffu, x, o);
        if ((tid & 31) >= o) x += y;
    }
    __shared__ int wsum[8];
    if ((tid & 31) == 31) wsum[tid >> 5] = x;
    __syncthreads();
    if (tid < 8) {
        int y = wsum[tid];
#pragma unroll
        for (int o = 1; o < 8; o <<= 1) {
            int z = __shfl_up_sync(0xffu, y, o);
            if (tid >= o) y += z;
        }
        wsum[tid] = y;
    }
    __syncthreads();
    int woff = (tid >= 32) ? wsum[(tid >> 5) - 1] : 0;
    int excl = x - sloc + woff;
    if (base < NN)     g_rs[base]     = excl;
    if (base + 1 < NN) g_rs[base + 1] = excl + v0;
    if (base + 2 < NN) g_rs[base + 2] = excl + v0 + v1;
    if (base + 3 < NN) g_rs[base + 3] = excl + v0 + v1 + v2;
    if (tid == 255) g_bsum[blockIdx.x] = excl + sloc;
}

__global__ void k_scan2(int nb) {
    int tid = threadIdx.x;
    int v = (tid < nb) ? g_bsum[tid] : 0;
    int x = v;
#pragma unroll
    for (int o = 1; o < 32; o <<= 1) {
        int y = __shfl_up_sync(0xffffffffu, x, o);
        if ((tid & 31) >= o) x += y;
    }
    __shared__ int ws[4];
    if ((tid & 31) == 31) ws[tid >> 5] = x;
    __syncthreads();
    int add = 0;
    for (int wq = 0; wq < (tid >> 5); wq++) add += ws[wq];
    x += add;
    if (tid < nb) g_bsum[tid] = x - v;
}

__global__ void k_scan3() {
    int i = blockIdx.x * 256 + threadIdx.x;
    if (i < NN) {
        int r = g_rs[i] + g_bsum[i >> 10];
        g_rs[i] = r;
        g_cur[i] = r;
    }
}

// ---------------- CSR fill ----------------
__global__ void k_fill(const int* __restrict__ src, const int* __restrict__ dst,
                       const float* __restrict__ attr, const float* __restrict__ atten) {
    int e2 = blockIdx.x * 256 + threadIdx.x;
    if (e2 * 2 >= NE) return;
    int2 s = *(const int2*)&src[e2 * 2];
    int2 d = *(const int2*)&dst[e2 * 2];
    float2 ar = *(const float2*)&attr[e2 * 2];
    float2 at = *(const float2*)&atten[e2 * 2];
    int p0 = atomicAdd(&g_cur[d.x], 1);
    g_ce[p0] = make_float2(__int_as_float(s.x), ar.x * at.x);
    g_catt[p0] = at.x;
    int p1 = atomicAdd(&g_cur[d.y], 1);
    g_ce[p1] = make_float2(__int_as_float(s.y), ar.y * at.y);
    g_catt[p1] = at.y;
}

// ---------------- row stats ----------------
__global__ void k_rowstats() {
    int gt = blockIdx.x * 256 + threadIdx.x;
    int node = gt >> 5, lane = gt & 31;
    if (node >= NN) return;
    int s = g_rs[node];
    int len = g_cnt[node];
    float wsum = 0.f, asum = 0.f;
    for (int i = lane; i < len; i += 32) {
        wsum += g_ce[s + i].y;
        asum += g_catt[s + i];
    }
#pragma unroll
    for (int o = 16; o > 0; o >>= 1) {
        wsum += __shfl_down_sync(0xffffffffu, wsum, o);
        asum += __shfl_down_sync(0xffffffffu, asum, o);
    }
    if (lane == 0) {
        g_Win[node] = wsum;
        float att_tot = asum + g_atts[node];
        float deg = (float)(len + g_degs[node]);
        g_natt[node] = att_tot / ((deg == 0.f) ? 1.f : deg);
    }
}

// ---------------- layer GEMM via mma.sync tf32 ----------------
// 256 threads / 8 warps. Warp: rowGroup = w&3 -> 32 rows (two m16 tiles),
// colHalf = w>>2 -> 32 cols of each of W1|W2|W3. B-frags reused across 2 row tiles.
// A(half) = h@W1+b1 ; D = h@W3+b3 - Win*(h@W2)
__global__ void __launch_bounds__(256, 2) k_gemm(const float* __restrict__ W1,
                                                 const float* __restrict__ W2,
                                                 const float* __restrict__ W3,
                                                 const float* __restrict__ b1,
                                                 const float* __restrict__ b3) {
    extern __shared__ float sm[];
    float* sh_h = sm;              // [128][68]
    float* sh_w = sm + 128 * 68;   // [64][200]
    int tid = threadIdx.x;
    int nbase = blockIdx.x * 128;

    for (int i = tid; i < 2048; i += 256) {
        int node = i >> 4, k4 = (i & 15) << 2;
        float4 v = make_float4(0.f, 0.f, 0.f, 0.f);
        int gn = nbase + node;
        if (gn < NN) v = *(const float4*)&g_h[gn * 64 + k4];
        uint32_t* p = (uint32_t*)&sh_h[node * 68 + k4];
        p[0] = f2tf32(v.x); p[1] = f2tf32(v.y); p[2] = f2tf32(v.z); p[3] = f2tf32(v.w);
    }
    for (int i = tid; i < 3072; i += 256) {
        int row = i / 48;
        int q = i % 48;
        int m = q >> 4, c4 = (q & 15) << 2;
        const float* Wm = (m == 0) ? W1 : ((m == 1) ? W2 : W3);
        float4 v = *(const float4*)&Wm[row * 64 + c4];
        uint32_t* p = (uint32_t*)&sh_w[row * 200 + m * 64 + c4];
        p[0] = f2tf32(v.x); p[1] = f2tf32(v.y); p[2] = f2tf32(v.z); p[3] = f2tf32(v.w);
    }
    __syncthreads();

    int w = tid >> 5, lane = tid & 31;
    int rowG = w & 3, colH = w >> 2;
    int gid = lane >> 2, tid4 = lane & 3;

    float acc[24][4];  // [rowTile(2) x mat(3) x ntile(4)][4]
#pragma unroll
    for (int t = 0; t < 24; t++) {
        acc[t][0] = 0.f; acc[t][1] = 0.f; acc[t][2] = 0.f; acc[t][3] = 0.f;
    }

    const uint32_t* hp = (const uint32_t*)(sh_h + rowG * 32 * 68);
    const uint32_t* wp = (const uint32_t*)sh_w;

#pragma unroll
    for (int kt = 0; kt < 8; kt++) {
        int k0 = kt * 8;
        uint32_t a[2][4];
#pragma unroll
        for (int rt = 0; rt < 2; rt++) {
            const uint32_t* hq = hp + rt * 16 * 68;
            a[rt][0] = hq[gid * 68 + k0 + tid4];
            a[rt][1] = hq[(gid + 8) * 68 + k0 + tid4];
            a[rt][2] = hq[gid * 68 + k0 + tid4 + 4];
            a[rt][3] = hq[(gid + 8) * 68 + k0 + tid4 + 4];
        }
#pragma unroll
        for (int m = 0; m < 3; m++) {
#pragma unroll
            for (int tt = 0; tt < 4; tt++) {
                int nb = m * 64 + colH * 32 + tt * 8;
                uint32_t bb0 = wp[(k0 + tid4) * 200 + nb + gid];
                uint32_t bb1 = wp[(k0 + tid4 + 4) * 200 + nb + gid];
#pragma unroll
                for (int rt = 0; rt < 2; rt++) {
                    float* c = acc[rt * 12 + m * 4 + tt];
                    asm volatile(
                        "mma.sync.aligned.m16n8k8.row.col.f32.tf32.tf32.f32 "
                        "{%0,%1,%2,%3}, {%4,%5,%6,%7}, {%8,%9}, {%0,%1,%2,%3};"
                        : "+f"(c[0]), "+f"(c[1]), "+f"(c[2]), "+f"(c[3])
                        : "r"(a[rt][0]), "r"(a[rt][1]), "r"(a[rt][2]), "r"(a[rt][3]),
                          "r"(bb0), "r"(bb1));
                }
            }
        }
    }

    // epilogue
#pragma unroll
    for (int rt = 0; rt < 2; rt++) {
        int r1 = nbase + rowG * 32 + rt * 16 + gid;
        int r2 = r1 + 8;
        float win1 = (r1 < NN) ? g_Win[r1] : 0.f;
        float win2 = (r2 < NN) ? g_Win[r2] : 0.f;
#pragma unroll
        for (int tt = 0; tt < 4; tt++) {
            int c = colH * 32 + tt * 8 + tid4 * 2;
            float2 b1v = *(const float2*)&b1[c];
            float2 b3v = *(const float2*)&b3[c];
            float* aW1 = acc[rt * 12 + tt];
            float* aW2 = acc[rt * 12 + 4 + tt];
            float* aW3 = acc[rt * 12 + 8 + tt];
            if (r1 < NN) {
                *(__half2*)&g_Ah[r1 * 64 + c] =
                    __floats2half2_rn(aW1[0] + b1v.x, aW1[1] + b1v.y);
                *(float2*)&g_D[r1 * 64 + c] = make_float2(aW3[0] + b3v.x - win1 * aW2[0],
                                                          aW3[1] + b3v.y - win1 * aW2[1]);
            }
            if (r2 < NN) {
                *(__half2*)&g_Ah[r2 * 64 + c] =
                    __floats2half2_rn(aW1[2] + b1v.x, aW1[3] + b1v.y);
                *(float2*)&g_D[r2 * 64 + c] = make_float2(aW3[2] + b3v.x - win2 * aW2[2],
                                                          aW3[3] + b3v.y - win2 * aW2[3]);
            }
        }
    }
}

// ---------------- gather: h = relu( sum_e w*A[src] + D ), warp per node ----------------
__global__ void k_gather() {
    int gt = blockIdx.x * 256 + threadIdx.x;
    int node = gt >> 5, lane = gt & 31;
    if (node >= NN) return;
    int s = g_rs[node];
    int e = s + g_cnt[node];
    int loff = lane * 2;
    float ax0 = 0.f, ay0 = 0.f, ax1 = 0.f, ay1 = 0.f;
    for (int base = s; base < e; base += 32) {
        int idx = base + lane;
        float2 ce = make_float2(0.f, 0.f);
        if (idx < e) ce = g_ce[idx];
        int sn = __float_as_int(ce.x);
        float wv = ce.y;
        int m = min(32, e - base);
        int mr = (m + 3) & ~3;
        for (int j = 0; j < mr; j += 4) {
            int s0 = __shfl_sync(0xffffffffu, sn, j);
            int s1 = __shfl_sync(0xffffffffu, sn, j + 1);
            int s2 = __shfl_sync(0xffffffffu, sn, j + 2);
            int s3 = __shfl_sync(0xffffffffu, sn, j + 3);
            float w0 = __shfl_sync(0xffffffffu, wv, j);
            float w1 = __shfl_sync(0xffffffffu, wv, j + 1);
            float w2 = __shfl_sync(0xffffffffu, wv, j + 2);
            float w3 = __shfl_sync(0xffffffffu, wv, j + 3);
            __half2 h0 = __ldg((const __half2*)&g_Ah[s0 * 64 + loff]);
            __half2 h1 = __ldg((const __half2*)&g_Ah[s1 * 64 + loff]);
            __half2 h2 = __ldg((const __half2*)&g_Ah[s2 * 64 + loff]);
            __half2 h3 = __ldg((const __half2*)&g_Ah[s3 * 64 + loff]);
            float2 v0 = __half22float2(h0);
            float2 v1 = __half22float2(h1);
            float2 v2 = __half22float2(h2);
            float2 v3 = __half22float2(h3);
            ax0 = fmaf(w0, v0.x, ax0); ay0 = fmaf(w0, v0.y, ay0);
            ax1 = fmaf(w1, v1.x, ax1); ay1 = fmaf(w1, v1.y, ay1);
            ax0 = fmaf(w2, v2.x, ax0); ay0 = fmaf(w2, v2.y, ay0);
            ax1 = fmaf(w3, v3.x, ax1); ay1 = fmaf(w3, v3.y, ay1);
        }
    }
    float2 dv = *(const float2*)&g_D[node * 64 + loff];
    float2 hv = make_float2(fmaxf(ax0 + ax1 + dv.x, 0.f), fmaxf(ay0 + ay1 + dv.y, 0.f));
    *(float2*)&g_h[node * 64 + loff] = hv;
}

// ---------------- pooling ----------------
__global__ void k_pool(const int* __restrict__ batch) {
    int g = blockIdx.x, tid = threadIdx.x;  // 64 threads
    __shared__ int se[2];
    if (tid < 2) {
        int key = g + tid;
        int lo = 0, hi = NN;
        while (lo < hi) {
            int mid = (lo + hi) >> 1;
            if (batch[mid] < key) lo = mid + 1; else hi = mid;
        }
        se[tid] = lo;
    }
    __syncthreads();
    int s = se[0], e = se[1];
    float acc = 0.f, att = 0.f;
    for (int i = s; i < e; i++) {
        float na = g_natt[i];
        acc = fmaf(g_h[i * 64 + tid], na, acc);
        att += na;
    }
    float cnt = (float)(e - s);
    float gat = (att == 0.f) ? 1.f : att;
    float scale = cnt / (gat * fmaxf(cnt, 1.f));
    g_gx[g * 64 + tid] = acc * scale;
}

// ---------------- final MLP ----------------
__global__ void k_mlp(const float* __restrict__ f1w, const float* __restrict__ f1b,
                      const float* __restrict__ f2w, const float* __restrict__ f2b,
                      float* __restrict__ out) {
    int g = blockIdx.x, tid = threadIdx.x;  // 128
    __shared__ float sx[64];
    __shared__ float shh[128];
    if (tid < 64) sx[tid] = g_gx[g * 64 + tid];
    __syncthreads();
    float a = f1b[tid];
#pragma unroll 8
    for (int k = 0; k < 64; k++) a = fmaf(sx[k], f1w[k * 128 + tid], a);
    shh[tid] = fmaxf(a, 0.f);
    __syncthreads();
    if (tid < 3) {
        float o = f2b[tid];
        for (int j = 0; j < 128; j++) o = fmaf(shh[j], f2w[j * 3 + tid], o);
        out[g * 3 + tid] = o;
    }
}

// ---------------- launch ----------------
extern "C" void kernel_launch(void* const* d_in, const int* in_sizes, int n_in,
                              void* d_out, int out_size) {
    const float* x     = (const float*)d_in[0];
    const int*   ei    = (const int*)d_in[1];
    const int*   batch = (const int*)d_in[2];
    const float* eattr = (const float*)d_in[3];
    const float* eatt  = (const float*)d_in[4];
    const float* embw  = (const float*)d_in[5];
    const float* embb  = (const float*)d_in[6];
    const float* l1w   = (const float*)d_in[7];
    const float* l1b   = (const float*)d_in[8];
    const float* l2w   = (const float*)d_in[9];
    const float* l3w   = (const float*)d_in[10];
    const float* l3b   = (const float*)d_in[11];
    const float* f1w   = (const float*)d_in[12];
    const float* f1b   = (const float*)d_in[13];
    const float* f2w   = (const float*)d_in[14];
    const float* f2b   = (const float*)d_in[15];
    float* out = (float*)d_out;

    const int smem_gemm = (128 * 68 + 64 * 200) * 4;  // 86016 B
    cudaFuncSetAttribute(k_gemm, cudaFuncAttributeMaxDynamicSharedMemorySize, smem_gemm);

    const int* src = ei;
    const int* dst = ei + NE;

    k_init<<<(NN * 64 + 255) / 256, 256>>>(x, embw, embb);
    k_edge<<<(NE / 4 + 255) / 256, 256>>>(src, dst, eatt);

    int nscan = (NN + 1023) / 1024;  // 98
    k_scan1<<<nscan, 256>>>();
    k_scan2<<<1, 128>>>(nscan);
    k_scan3<<<(NN + 255) / 256, 256>>>();
    k_fill<<<(NE / 2 + 255) / 256, 256>>>(src, dst, eattr, eatt);
    k_rowstats<<<(NN * 32 + 255) / 256, 256>>>();

    for (int l = 0; l < 3; l++) {
        k_gemm<<<(NN + 127) / 128, 256, smem_gemm>>>(
            l1w + l * 4096, l2w + l * 4096, l3w + l * 4096,
            l1b + l * 64, l3b + l * 64);
        k_gather<<<(NN * 32 + 255) / 256, 256>>>();
    }

    k_pool<<<NGR, 64>>>(batch);
    k_mlp<<<NGR, 128>>>(f1w, f1b, f2w, f2b, out);
}

// round 6
// speedup vs baseline: 1.5974x; 1.0183x over previous
#include <cuda_runtime.h>
#include <cuda_fp16.h>
#include <cstdint>

#define NN 100000
#define NE 1000000
#define NGR 512

// ---------------- scratch ----------------
__device__ float g_Win[NN];
__device__ float g_atts[NN];
__device__ int   g_degs[NN];
__device__ float g_natt[NN];
__device__ int   g_cnt[NN];
__device__ int   g_rs[NN];
__device__ int   g_cur[NN];
__device__ int   g_bsum[128];     // chained-scan flags: 0=not ready, else incl+1
__device__ int   g_tick;
__device__ float2 g_ce[NE];       // CSR: {src_as_bits, w}
__device__ float g_catt[NE];
__device__ __half g_hh[NN * 64];  // h in fp16
__device__ __half g_Ah[NN * 64];  // A in fp16
__device__ __half g_Dh[NN * 64];  // D in fp16

__device__ __forceinline__ uint32_t f2tf32(float f) {
    uint32_t o;
    asm("cvt.rna.tf32.f32 %0, %1;" : "=r"(o) : "f"(f));
    return o;
}

// ---------------- init: zero scratch + node embedding (h fp16) ----------------
__global__ void k_init(const float* __restrict__ x, const float* __restrict__ w,
                       const float* __restrict__ b) {
    int gid = blockIdx.x * 256 + threadIdx.x;
    if (gid < NN) { g_atts[gid] = 0.f; g_degs[gid] = 0; g_cnt[gid] = 0; }
    if (gid < 128) g_bsum[gid] = 0;
    if (gid == 0) g_tick = 0;
    if (gid < NN * 32) {
        int i = gid >> 5, c = (gid & 31) * 2;
        float x0 = x[i * 4], x1 = x[i * 4 + 1], x2 = x[i * 4 + 2], x3 = x[i * 4 + 3];
        float h0 = b[c]     + x0 * w[c]     + x1 * w[64 + c]     + x2 * w[128 + c]     + x3 * w[192 + c];
        float h1 = b[c + 1] + x0 * w[c + 1] + x1 * w[64 + c + 1] + x2 * w[128 + c + 1] + x3 * w[192 + c + 1];
        *(__half2*)&g_hh[i * 64 + c] = __floats2half2_rn(h0, h1);
    }
}

// ---------------- edge pass: dst in-degree histogram only ----------------
__global__ void k_edge(const int* __restrict__ dst) {
    int e4 = blockIdx.x * 256 + threadIdx.x;
    if (e4 * 4 >= NE) return;
    int4 d = *(const int4*)&dst[e4 * 4];
    atomicAdd(&g_cnt[d.x], 1); atomicAdd(&g_cnt[d.y], 1);
    atomicAdd(&g_cnt[d.z], 1); atomicAdd(&g_cnt[d.w], 1);
}

// ---------------- single-pass chained exclusive scan: g_cnt -> g_rs, g_cur ----
__global__ void k_scan() {
    __shared__ int sm_t, sm_prev, wsum[8];
    int tid = threadIdx.x;
    if (tid == 0) sm_t = atomicAdd(&g_tick, 1);
    __syncthreads();
    int t = sm_t;
    int base = t * 1024 + tid * 4;
    int v0 = 0, v1 = 0, v2 = 0, v3 = 0;
    if (base + 3 < NN) {
        int4 q = *(const int4*)&g_cnt[base];
        v0 = q.x; v1 = q.y; v2 = q.z; v3 = q.w;
    } else {
        if (base < NN)     v0 = g_cnt[base];
        if (base + 1 < NN) v1 = g_cnt[base + 1];
        if (base + 2 < NN) v2 = g_cnt[base + 2];
        if (base + 3 < NN) v3 = g_cnt[base + 3];
    }
    int sloc = v0 + v1 + v2 + v3;
    int x = sloc;
#pragma unroll
    for (int o = 1; o < 32; o <<= 1) {
        int y = __shfl_up_sync(0xffffffffu, x, o);
        if ((tid & 31) >= o) x += y;
    }
    if ((tid & 31) == 31) wsum[tid >> 5] = x;
    __syncthreads();
    if (tid < 8) {
        int y = wsum[tid];
#pragma unroll
        for (int o = 1; o < 8; o <<= 1) {
            int z = __shfl_up_sync(0xffu, y, o);
            if (tid >= o) y += z;
        }
        wsum[tid] = y;
    }
    __syncthreads();
    int woff = (tid >= 32) ? wsum[(tid >> 5) - 1] : 0;
    int excl = x - sloc + woff;
    int total = wsum[7];  // block total
    if (tid == 0) {
        int prev = 0;
        if (t > 0) {
            int v;
            while ((v = atomicAdd(&g_bsum[t - 1], 0)) == 0) {}
            prev = v - 1;
        }
        atomicExch(&g_bsum[t], prev + total + 1);
        sm_prev = prev;
    }
    __syncthreads();
    int off = sm_prev + excl;
    if (base < NN)     { g_rs[base]     = off;               g_cur[base]     = off; }
    if (base + 1 < NN) { g_rs[base + 1] = off + v0;           g_cur[base + 1] = off + v0; }
    if (base + 2 < NN) { g_rs[base + 2] = off + v0 + v1;      g_cur[base + 2] = off + v0 + v1; }
    if (base + 3 < NN) { g_rs[base + 3] = off + v0 + v1 + v2; g_cur[base + 3] = off + v0 + v1 + v2; }
}

// ---------------- CSR fill + src-side atomics ----------------
__global__ void k_fill(const int* __restrict__ src, const int* __restrict__ dst,
                       const float* __restrict__ attr, const float* __restrict__ atten) {
    int e2 = blockIdx.x * 256 + threadIdx.x;
    if (e2 * 2 >= NE) return;
    int2 s = *(const int2*)&src[e2 * 2];
    int2 d = *(const int2*)&dst[e2 * 2];
    float2 ar = *(const float2*)&attr[e2 * 2];
    float2 at = *(const float2*)&atten[e2 * 2];
    int p0 = atomicAdd(&g_cur[d.x], 1);
    g_ce[p0] = make_float2(__int_as_float(s.x), ar.x * at.x);
    g_catt[p0] = at.x;
    int p1 = atomicAdd(&g_cur[d.y], 1);
    g_ce[p1] = make_float2(__int_as_float(s.y), ar.y * at.y);
    g_catt[p1] = at.y;
    atomicAdd(&g_atts[s.x], at.x); atomicAdd(&g_atts[s.y], at.y);
    atomicAdd(&g_degs[s.x], 1);    atomicAdd(&g_degs[s.y], 1);
}

// ---------------- row stats ----------------
__global__ void k_rowstats() {
    int gt = blockIdx.x * 256 + threadIdx.x;
    int node = gt >> 5, lane = gt & 31;
    if (node >= NN) return;
    int s = g_rs[node];
    int len = g_cnt[node];
    float wsum = 0.f, asum = 0.f;
    for (int i = lane; i < len; i += 32) {
        wsum += g_ce[s + i].y;
        asum += g_catt[s + i];
    }
#pragma unroll
    for (int o = 16; o > 0; o >>= 1) {
        wsum += __shfl_down_sync(0xffffffffu, wsum, o);
        asum += __shfl_down_sync(0xffffffffu, asum, o);
    }
    if (lane == 0) {
        g_Win[node] = wsum;
        float att_tot = asum + g_atts[node];
        float deg = (float)(len + g_degs[node]);
        g_natt[node] = att_tot / ((deg == 0.f) ? 1.f : deg);
    }
}

// ---------------- layer GEMM via mma.sync tf32 (h fp16 in, A/D fp16 out) -----
__global__ void __launch_bounds__(256, 2) k_gemm(const float* __restrict__ W1,
                                                 const float* __restrict__ W2,
                                                 const float* __restrict__ W3,
                                                 const float* __restrict__ b1,
                                                 const float* __restrict__ b3) {
    extern __shared__ float sm[];
    float* sh_h = sm;              // [128][68] tf32 words
    float* sh_w = sm + 128 * 68;   // [64][200]
    int tid = threadIdx.x;
    int nbase = blockIdx.x * 128;

    // h tile: 16B loads (8 halves), exact fp16->tf32 convert
    for (int i = tid; i < 1024; i += 256) {
        int node = i >> 3, k8 = (i & 7) << 3;
        int gn = nbase + node;
        uint4 v = make_uint4(0u, 0u, 0u, 0u);
        if (gn < NN) v = *(const uint4*)&g_hh[gn * 64 + k8];
        __half2* hv = (__half2*)&v;
        uint32_t* p = (uint32_t*)&sh_h[node * 68 + k8];
#pragma unroll
        for (int j = 0; j < 4; j++) {
            float2 f = __half22float2(hv[j]);
            p[2 * j] = f2tf32(f.x); p[2 * j + 1] = f2tf32(f.y);
        }
    }
    for (int i = tid; i < 3072; i += 256) {
        int row = i / 48;
        int q = i % 48;
        int m = q >> 4, c4 = (q & 15) << 2;
        const float* Wm = (m == 0) ? W1 : ((m == 1) ? W2 : W3);
        float4 v = *(const float4*)&Wm[row * 64 + c4];
        uint32_t* p = (uint32_t*)&sh_w[row * 200 + m * 64 + c4];
        p[0] = f2tf32(v.x); p[1] = f2tf32(v.y); p[2] = f2tf32(v.z); p[3] = f2tf32(v.w);
    }
    __syncthreads();

    int w = tid >> 5, lane = tid & 31;
    int rowG = w & 3, colH = w >> 2;
    int gid = lane >> 2, tid4 = lane & 3;

    float acc[24][4];
#pragma unroll
    for (int t = 0; t < 24; t++) {
        acc[t][0] = 0.f; acc[t][1] = 0.f; acc[t][2] = 0.f; acc[t][3] = 0.f;
    }

    const uint32_t* hp = (const uint32_t*)(sh_h + rowG * 32 * 68);
    const uint32_t* wp = (const uint32_t*)sh_w;

#pragma unroll
    for (int kt = 0; kt < 8; kt++) {
        int k0 = kt * 8;
        uint32_t a[2][4];
#pragma unroll
        for (int rt = 0; rt < 2; rt++) {
            const uint32_t* hq = hp + rt * 16 * 68;
            a[rt][0] = hq[gid * 68 + k0 + tid4];
            a[rt][1] = hq[(gid + 8) * 68 + k0 + tid4];
            a[rt][2] = hq[gid * 68 + k0 + tid4 + 4];
            a[rt][3] = hq[(gid + 8) * 68 + k0 + tid4 + 4];
        }
#pragma unroll
        for (int m = 0; m < 3; m++) {
#pragma unroll
            for (int tt = 0; tt < 4; tt++) {
                int nb = m * 64 + colH * 32 + tt * 8;
                uint32_t bb0 = wp[(k0 + tid4) * 200 + nb + gid];
                uint32_t bb1 = wp[(k0 + tid4 + 4) * 200 + nb + gid];
#pragma unroll
                for (int rt = 0; rt < 2; rt++) {
                    float* c = acc[rt * 12 + m * 4 + tt];
                    asm volatile(
                        "mma.sync.aligned.m16n8k8.row.col.f32.tf32.tf32.f32 "
                        "{%0,%1,%2,%3}, {%4,%5,%6,%7}, {%8,%9}, {%0,%1,%2,%3};"
                        : "+f"(c[0]), "+f"(c[1]), "+f"(c[2]), "+f"(c[3])
                        : "r"(a[rt][0]), "r"(a[rt][1]), "r"(a[rt][2]), "r"(a[rt][3]),
                          "r"(bb0), "r"(bb1));
                }
            }
        }
    }

#pragma unroll
    for (int rt = 0; rt < 2; rt++) {
        int r1 = nbase + rowG * 32 + rt * 16 + gid;
        int r2 = r1 + 8;
        float win1 = (r1 < NN) ? g_Win[r1] : 0.f;
        float win2 = (r2 < NN) ? g_Win[r2] : 0.f;
#pragma unroll
        for (int tt = 0; tt < 4; tt++) {
            int c = colH * 32 + tt * 8 + tid4 * 2;
            float2 b1v = *(const float2*)&b1[c];
            float2 b3v = *(const float2*)&b3[c];
            float* aW1 = acc[rt * 12 + tt];
            float* aW2 = acc[rt * 12 + 4 + tt];
            float* aW3 = acc[rt * 12 + 8 + tt];
            if (r1 < NN) {
                *(__half2*)&g_Ah[r1 * 64 + c] =
                    __floats2half2_rn(aW1[0] + b1v.x, aW1[1] + b1v.y);
                *(__half2*)&g_Dh[r1 * 64 + c] =
                    __floats2half2_rn(aW3[0] + b3v.x - win1 * aW2[0],
                                      aW3[1] + b3v.y - win1 * aW2[1]);
            }
            if (r2 < NN) {
                *(__half2*)&g_Ah[r2 * 64 + c] =
                    __floats2half2_rn(aW1[2] + b1v.x, aW1[3] + b1v.y);
                *(__half2*)&g_Dh[r2 * 64 + c] =
                    __floats2half2_rn(aW3[2] + b3v.x - win2 * aW2[2],
                                      aW3[3] + b3v.y - win2 * aW2[3]);
            }
        }
    }
}

// ---------------- gather: h = relu( sum_e w*A[src] + D ), warp per node ------
__global__ void k_gather() {
    int gt = blockIdx.x * 256 + threadIdx.x;
    int node = gt >> 5, lane = gt & 31;
    if (node >= NN) return;
    int s = g_rs[node];
    int e = s + g_cnt[node];
    int loff = lane * 2;
    float ax0 = 0.f, ay0 = 0.f, ax1 = 0.f, ay1 = 0.f;
    for (int base = s; base < e; base += 32) {
        int idx = base + lane;
        float2 ce = make_float2(0.f, 0.f);
        if (idx < e) ce = g_ce[idx];
        int sn = __float_as_int(ce.x);
        float wv = ce.y;
        int m = min(32, e - base);
        int mr = (m + 3) & ~3;
        for (int j = 0; j < mr; j += 4) {
            int s0 = __shfl_sync(0xffffffffu, sn, j);
            int s1 = __shfl_sync(0xffffffffu, sn, j + 1);
            int s2 = __shfl_sync(0xffffffffu, sn, j + 2);
            int s3 = __shfl_sync(0xffffffffu, sn, j + 3);
            float w0 = __shfl_sync(0xffffffffu, wv, j);
            float w1 = __shfl_sync(0xffffffffu, wv, j + 1);
            float w2 = __shfl_sync(0xffffffffu, wv, j + 2);
            float w3 = __shfl_sync(0xffffffffu, wv, j + 3);
            __half2 h0 = __ldg((const __half2*)&g_Ah[s0 * 64 + loff]);
            __half2 h1 = __ldg((const __half2*)&g_Ah[s1 * 64 + loff]);
            __half2 h2 = __ldg((const __half2*)&g_Ah[s2 * 64 + loff]);
            __half2 h3 = __ldg((const __half2*)&g_Ah[s3 * 64 + loff]);
            float2 v0 = __half22float2(h0);
            float2 v1 = __half22float2(h1);
            float2 v2 = __half22float2(h2);
            float2 v3 = __half22float2(h3);
            ax0 = fmaf(w0, v0.x, ax0); ay0 = fmaf(w0, v0.y, ay0);
            ax1 = fmaf(w1, v1.x, ax1); ay1 = fmaf(w1, v1.y, ay1);
            ax0 = fmaf(w2, v2.x, ax0); ay0 = fmaf(w2, v2.y, ay0);
            ax1 = fmaf(w3, v3.x, ax1); ay1 = fmaf(w3, v3.y, ay1);
        }
    }
    float2 dv = __half22float2(*(const __half2*)&g_Dh[node * 64 + loff]);
    *(__half2*)&g_hh[node * 64 + loff] =
        __floats2half2_rn(fmaxf(ax0 + ax1 + dv.x, 0.f), fmaxf(ay0 + ay1 + dv.y, 0.f));
}

// ---------------- fused pooling + MLP (one block per graph, 128 threads) -----
__global__ void k_poolmlp(const int* __restrict__ batch,
                          const float* __restrict__ f1w, const float* __restrict__ f1b,
                          const float* __restrict__ f2w, const float* __restrict__ f2b,
                          float* __restrict__ out) {
    int g = blockIdx.x, tid = threadIdx.x;  // 128
    __shared__ int se[2];
    __shared__ float sacc[128], satt[128];
    __shared__ float sx[64], shh[128];
    if (tid < 2) {
        int key = g + tid;
        int lo = 0, hi = NN;
        while (lo < hi) {
            int mid = (lo + hi) >> 1;
            if (batch[mid] < key) lo = mid + 1; else hi = mid;
        }
        se[tid] = lo;
    }
    __syncthreads();
    int s = se[0], e = se[1];
    int c = tid & 63, part = tid >> 6;
    float acc = 0.f, att = 0.f;
    for (int i = s + part; i < e; i += 2) {
        float na = g_natt[i];
        acc = fmaf(__half2float(g_hh[i * 64 + c]), na, acc);
        att += na;
    }
    sacc[tid] = acc; satt[tid] = att;
    __syncthreads();
    if (tid < 64) {
        float a = sacc[tid] + sacc[tid + 64];
        float at = satt[0] + satt[64];
        float cnt = (float)(e - s);
        float gat = (at == 0.f) ? 1.f : at;
        float scale = cnt / (gat * fmaxf(cnt, 1.f));
        sx[tid] = a * scale;
    }
    __syncthreads();
    float a = f1b[tid];
#pragma unroll 8
    for (int k = 0; k < 64; k++) a = fmaf(sx[k], f1w[k * 128 + tid], a);
    shh[tid] = fmaxf(a, 0.f);
    __syncthreads();
    if (tid < 3) {
        float o = f2b[tid];
        for (int j = 0; j < 128; j++) o = fmaf(shh[j], f2w[j * 3 + tid], o);
        out[g * 3 + tid] = o;
    }
}

// ---------------- launch ----------------
extern "C" void kernel_launch(void* const* d_in, const int* in_sizes, int n_in,
                              void* d_out, int out_size) {
    const float* x     = (const float*)d_in[0];
    const int*   ei    = (const int*)d_in[1];
    const int*   batch = (const int*)d_in[2];
    const float* eattr = (const float*)d_in[3];
    const float* eatt  = (const float*)d_in[4];
    const float* embw  = (const float*)d_in[5];
    const float* embb  = (const float*)d_in[6];
    const float* l1w   = (const float*)d_in[7];
    const float* l1b   = (const float*)d_in[8];
    const float* l2w   = (const float*)d_in[9];
    const float* l3w   = (const float*)d_in[10];
    const float* l3b   = (const float*)d_in[11];
    const float* f1w   = (const float*)d_in[12];
    const float* f1b   = (const float*)d_in[13];
    const float* f2w   = (const float*)d_in[14];
    const float* f2b   = (const float*)d_in[15];
    float* out = (float*)d_out;

    const int smem_gemm = (128 * 68 + 64 * 200) * 4;  // 86016 B
    cudaFuncSetAttribute(k_gemm, cudaFuncAttributeMaxDynamicSharedMemorySize, smem_gemm);

    const int* src = ei;
    const int* dst = ei + NE;

    k_init<<<(NN * 32 + 255) / 256, 256>>>(x, embw, embb);
    k_edge<<<(NE / 4 + 255) / 256, 256>>>(dst);
    k_scan<<<(NN + 1023) / 1024, 256>>>();
    k_fill<<<(NE / 2 + 255) / 256, 256>>>(src, dst, eattr, eatt);
    k_rowstats<<<(NN * 32 + 255) / 256, 256>>>();

    for (int l = 0; l < 3; l++) {
        k_gemm<<<(NN + 127) / 128, 256, smem_gemm>>>(
            l1w + l * 4096, l2w + l * 4096, l3w + l * 4096,
            l1b + l * 64, l3b + l * 64);
        k_gather<<<(NN * 32 + 255) / 256, 256>>>();
    }

    k_poolmlp<<<NGR, 128>>>(batch, f1w, f1b, f2w, f2b, out);
}